// round 13
// baseline (speedup 1.0000x reference)
#include <cuda_runtime.h>
#include <math.h>

typedef unsigned long long ull;
#define IMG 256

__device__ float gZ [IMG*256*64];
__device__ float gY [IMG*64*64];
__device__ float gF [IMG*64*64];
__device__ float gT [IMG*256*64];
__device__ float gW1[128*64];
__device__ float gTb[256*68];
__device__ float gTAT[66*256];
__device__ float gWB2[64*128];

__device__ __forceinline__ ull pk(float x) {
    ull r; unsigned xi = __float_as_uint(x);
    asm("mov.b64 %0, {%1, %1};" : "=l"(r) : "r"(xi));
    return r;
}
__device__ __forceinline__ void fma2(ull& d, ull a, ull b) {
    asm("fma.rn.f32x2 %0, %1, %2, %0;" : "+l"(d) : "l"(a), "l"(b));
}
__device__ __forceinline__ float2 uf(ull v) {
    float2 f; asm("mov.b64 {%0, %1}, %2;" : "=f"(f.x), "=f"(f.y) : "l"(v));
    return f;
}
__device__ __forceinline__ int k2map(int p) { return (p < 16) ? 2 * p : 2 * (p - 16) + 1; }

__global__ void k_tables() {
    int idx = blockIdx.x * 256 + threadIdx.x;  // 69*256
    const float W0 = 6.2831853071795864769f / 256.0f;
    if (idx < 8192) {           // gW1 [w<128][c p-order]
        int w = idx >> 6, c = idx & 63;
        int k2 = k2map(c >> 1);
        float s, cc; sincosf(((k2 * w) & 255) * W0, &s, &cc);
        gW1[idx] = (c & 1) ? -s : cc;
    }
    if (idx < 256 * 68) {       // gTb [h][2t+s], t<=32
        int h = idx / 68, tr = idx % 68;
        int t = tr >> 1; float v = 0.f;
        if (t <= 32) { float s, cc; sincosf(((t * h) & 255) * W0, &s, &cc); v = (tr & 1) ? s : cc; }
        gTb[idx] = v;
    }
    if (idx < 66 * 256) {       // gTAT [k<66][h] /16
        int k = idx >> 8, h = idx & 255;
        int t = k >> 1;
        float s, cc; sincosf(((t * h) & 255) * W0, &s, &cc);
        gTAT[idx] = ((k & 1) ? s : cc) * 0.0625f;
    }
    if (idx < 8192) {           // gWB2 [kk p-order][w<128]
        int kk = idx >> 7, w = idx & 127;
        int k2 = k2map(kk >> 1);
        float s, cc; sincosf(((k2 * w) & 255) * W0, &s, &cc);
        float v;
        if ((kk & 1) == 0) v = ((k2 == 0) ? 1.0f : 2.0f) * 0.0625f * cc;
        else               v = (k2 == 0) ? 0.0f : -0.125f * s;
        gWB2[idx] = v;
    }
}

// F1: 64 rows x 64 cols per block (1024 blocks, 128 threads), K=128 in 8 chunks of 16.
__global__ void __launch_bounds__(128) k_f1(const float* __restrict__ x) {
    __shared__ __align__(16) float Ut[16 * 64];   // [k][row^swz]
    __shared__ __align__(16) float Vt[16 * 64];
    __shared__ __align__(16) float Ws[128 * 64];  // [w][c]
    int tid = threadIdx.x;
    size_t r0 = (size_t)blockIdx.x * 64;
    for (int i = tid; i < 2048; i += 128)
        ((float4*)Ws)[i] = ((const float4*)gW1)[i];
    int ty = tid >> 3, tx = tid & 7;      // compute: rows ty*4..+3 (ty 0..15), cols tx
    int q = tid & 3, srow = tid >> 2;     // staging: q 0..3, srow 0..31
    int pr0 = srow ^ (q << 3), pr1 = (srow + 32) ^ (q << 3), kb = q * 4;
    float4 pa0, pb0, pa1, pb1;
    {
        const float* xp0 = x + (r0 + srow) * 256 + q * 4;
        const float* xp1 = x + (r0 + srow + 32) * 256 + q * 4;
        pa0 = *(const float4*)xp0; pb0 = *(const float4*)(xp0 + 128);
        pa1 = *(const float4*)xp1; pb1 = *(const float4*)(xp1 + 128);
    }
    ull acc[4][4] = {};
    for (int kt = 0; kt < 8; kt++) {
        __syncthreads();   // prev compute done (and Ws ready on kt=0)
        Ut[(kb + 0) * 64 + pr0] = pa0.x + pb0.x; Vt[(kb + 0) * 64 + pr0] = pa0.x - pb0.x;
        Ut[(kb + 1) * 64 + pr0] = pa0.y + pb0.y; Vt[(kb + 1) * 64 + pr0] = pa0.y - pb0.y;
        Ut[(kb + 2) * 64 + pr0] = pa0.z + pb0.z; Vt[(kb + 2) * 64 + pr0] = pa0.z - pb0.z;
        Ut[(kb + 3) * 64 + pr0] = pa0.w + pb0.w; Vt[(kb + 3) * 64 + pr0] = pa0.w - pb0.w;
        Ut[(kb + 0) * 64 + pr1] = pa1.x + pb1.x; Vt[(kb + 0) * 64 + pr1] = pa1.x - pb1.x;
        Ut[(kb + 1) * 64 + pr1] = pa1.y + pb1.y; Vt[(kb + 1) * 64 + pr1] = pa1.y - pb1.y;
        Ut[(kb + 2) * 64 + pr1] = pa1.z + pb1.z; Vt[(kb + 2) * 64 + pr1] = pa1.z - pb1.z;
        Ut[(kb + 3) * 64 + pr1] = pa1.w + pb1.w; Vt[(kb + 3) * 64 + pr1] = pa1.w - pb1.w;
        __syncthreads();
        if (kt < 7) {
            const float* xp0 = x + (r0 + srow) * 256 + (kt + 1) * 16 + q * 4;
            const float* xp1 = x + (r0 + srow + 32) * 256 + (kt + 1) * 16 + q * 4;
            pa0 = *(const float4*)xp0; pb0 = *(const float4*)(xp0 + 128);
            pa1 = *(const float4*)xp1; pb1 = *(const float4*)(xp1 + 128);
        }
        #pragma unroll 4
        for (int k = 0; k < 16; k++) {
            int sw = ((k >> 2) & 3) << 3;
            int ar_ = (ty * 4) ^ sw;
            float4 au = *(const float4*)&Ut[k * 64 + ar_];
            float4 av = *(const float4*)&Vt[k * 64 + ar_];
            const float* Wk = Ws + (kt * 16 + k) * 64;
            ulonglong2 BU = *(const ulonglong2*)&Wk[tx * 4];
            ulonglong2 BV = *(const ulonglong2*)&Wk[32 + tx * 4];
            ull pu0 = pk(au.x), pu1 = pk(au.y), pu2 = pk(au.z), pu3 = pk(au.w);
            ull pv0 = pk(av.x), pv1 = pk(av.y), pv2 = pk(av.z), pv3 = pk(av.w);
            fma2(acc[0][0], pu0, BU.x); fma2(acc[0][1], pu0, BU.y);
            fma2(acc[1][0], pu1, BU.x); fma2(acc[1][1], pu1, BU.y);
            fma2(acc[2][0], pu2, BU.x); fma2(acc[2][1], pu2, BU.y);
            fma2(acc[3][0], pu3, BU.x); fma2(acc[3][1], pu3, BU.y);
            fma2(acc[0][2], pv0, BV.x); fma2(acc[0][3], pv0, BV.y);
            fma2(acc[1][2], pv1, BV.x); fma2(acc[1][3], pv1, BV.y);
            fma2(acc[2][2], pv2, BV.x); fma2(acc[2][3], pv2, BV.y);
            fma2(acc[3][2], pv3, BV.x); fma2(acc[3][3], pv3, BV.y);
        }
    }
    #pragma unroll
    for (int i = 0; i < 4; i++) {
        float* o = &gZ[(r0 + ty * 4 + i) * 64];
        float2 u0 = uf(acc[i][0]), u1 = uf(acc[i][1]);
        float2 v0 = uf(acc[i][2]), v1 = uf(acc[i][3]);
        *(float4*)&o[tx * 4]      = make_float4(u0.x, u0.y, u1.x, u1.y);
        *(float4*)&o[32 + tx * 4] = make_float4(v0.x, v0.y, v1.x, v1.y);
    }
}

// F2: grid (img, colhalf). out rows 2t(cos)/2t+1(sin) per thread, reconstruct Y(+t)/Y(-t).
__global__ void __launch_bounds__(288) k_f2() {
    __shared__ float Tbs[64 * 68];
    __shared__ float Zs[64 * 32];
    int tid = threadIdx.x;
    int bi = blockIdx.x;             // 512
    int img = bi >> 1, ch = bi & 1;
    int ty = tid >> 3, tx = tid & 7;
    int tyc = (ty <= 32) ? ty : 32;
    ull acc[2][2] = {};
    for (int hc = 0; hc < 4; hc++) {
        __syncthreads();
        for (int i = tid; i < 512; i += 288) {
            int row = i >> 3, q = i & 7;
            *(float4*)&Zs[row * 32 + q * 4] =
                *(const float4*)&gZ[((size_t)img * 256 + hc * 64 + row) * 64 + ch * 32 + q * 4];
        }
        for (int i = tid; i < 1088; i += 288) {
            int row = i / 17, q = i % 17;
            *(float4*)&Tbs[row * 68 + q * 4] = *(const float4*)&gTb[(hc * 64 + row) * 68 + q * 4];
        }
        __syncthreads();
        #pragma unroll 4
        for (int k = 0; k < 64; k++) {
            float2 a = *(const float2*)&Tbs[k * 68 + tyc * 2];
            ulonglong2 B = *(const ulonglong2*)&Zs[k * 32 + tx * 4];
            ull pc = pk(a.x), ps = pk(a.y);
            fma2(acc[0][0], pc, B.x); fma2(acc[0][1], pc, B.y);
            fma2(acc[1][0], ps, B.x); fma2(acc[1][1], ps, B.y);
        }
    }
    if (ty <= 32) {
        int t = ty;
        float2 C0 = uf(acc[0][0]), C1 = uf(acc[0][1]);
        float2 S0 = uf(acc[1][0]), S1 = uf(acc[1][1]);
        const float n = 0.00390625f;
        float4 yp = make_float4((C0.x + S0.y) * n, (C0.y - S0.x) * n,
                                (C1.x + S1.y) * n, (C1.y - S1.x) * n);
        float4 ym = make_float4((C0.x - S0.y) * n, (C0.y + S0.x) * n,
                                (C1.x - S1.y) * n, (C1.y + S1.x) * n);
        int c = ch * 32 + tx * 4;
        if (t < 32) *(float4*)&gY[((size_t)img * 64 + t) * 64 + c] = yp;
        if (t >= 1) *(float4*)&gY[((size_t)img * 64 + (64 - t)) * 64 + c] = ym;
    }
}

// Mix (+ fused kernel^r and G). grid 512: (k1i, q, batch-half); 128 threads.
__global__ void __launch_bounds__(128) k_mix(const float* __restrict__ kern, const float* __restrict__ rp) {
    __shared__ float Ys[4][32][16];
    __shared__ float Gr[32][9], Gi[32][9];
    __shared__ float tw[64];
    int tid = threadIdx.x;
    int bi = blockIdx.x;             // 512
    int k1i = bi >> 3, q = (bi >> 1) & 3, bh = bi & 1;
    int s_ = (k1i < 32) ? 0 : 1;
    int m1 = k1i & 31;
    int b = tid >> 5, c = tid & 31;  // b 0..3 local
    if (tid < 32) {
        float s, cc; sincosf(tid * (6.2831853071795864769f / 32.0f), &s, &cc);
        tw[2 * tid] = cc; tw[2 * tid + 1] = s;
    }
    {
        const float4* ysrc = (const float4*)(gY + ((size_t)((bh * 4 + b) * 32 + c) * 64 + k1i) * 64 + q * 16);
        float4* dst = (float4*)&Ys[b][c][0];
        #pragma unroll
        for (int t = 0; t < 4; t++) dst[t] = ysrc[t];
    }
    __syncthreads();   // tw ready
    {
        int d = tid >> 2, kq2 = (tid & 3) * 2;       // each thread: 2 adjacent kq
        int m2a = k2map(q * 8 + kq2), m2b = k2map(q * 8 + kq2 + 1);
        float r = *rp;
        float ar0 = 0.f, ai0 = 0.f, ar1 = 0.f, ai1 = 0.f;
        const float* kpa = kern + (((size_t)(s_ * 32) * 32 + m1) * 32 + m2a) * 2;
        const float* kpb = kern + (((size_t)(s_ * 32) * 32 + m1) * 32 + m2b) * 2;
        #pragma unroll 4
        for (int j = 0; j < 32; j++) {
            float cra = kpa[j * 2048], cia = kpa[j * 2048 + 1];
            float crb = kpb[j * 2048], cib = kpb[j * 2048 + 1];
            if (r != 1.0f) {
                float mv = cra * cra + cia * cia;
                if (mv == 0.0f) { cra = 0.0f; cia = 0.0f; }
                else {
                    float mag = expf(0.5f * r * logf(mv));
                    float th = atan2f(cia, cra) * r;
                    float sn, cs; sincosf(th, &sn, &cs);
                    cra = mag * cs; cia = mag * sn;
                }
                mv = crb * crb + cib * cib;
                if (mv == 0.0f) { crb = 0.0f; cib = 0.0f; }
                else {
                    float mag = expf(0.5f * r * logf(mv));
                    float th = atan2f(cib, crb) * r;
                    float sn, cs; sincosf(th, &sn, &cs);
                    crb = mag * cs; cib = mag * sn;
                }
            }
            int a = (j * d) & 31;
            float twr = tw[2 * a], twi = tw[2 * a + 1];
            ar0 += twr * cra - twi * cia;  ai0 += twr * cia + twi * cra;
            ar1 += twr * crb - twi * cib;  ai1 += twr * cib + twi * crb;
        }
        Gr[d][kq2] = ar0 * 0.03125f;     Gi[d][kq2] = ai0 * 0.03125f;
        Gr[d][kq2 + 1] = ar1 * 0.03125f; Gi[d][kq2 + 1] = ai1 * 0.03125f;
    }
    __syncthreads();
    float ar[8] = {}, ai[8] = {};
    for (int cc = 0; cc < 32; cc++) {
        int d = (c - cc) & 31;
        #pragma unroll
        for (int kq = 0; kq < 8; kq++) {
            float gr = Gr[d][kq], gim = Gi[d][kq];
            float yr = Ys[b][cc][2 * kq], yi = Ys[b][cc][2 * kq + 1];
            ar[kq] += gr * yr - gim * yi;
            ai[kq] += gr * yi + gim * yr;
        }
    }
    float* fo = gF + ((size_t)((bh * 4 + b) * 32 + c) * 64 + k1i) * 64 + q * 16;
    #pragma unroll
    for (int kq = 0; kq < 8; kq++) { fo[2 * kq] = ar[kq]; fo[2 * kq + 1] = ai[kq]; }
}

// I1: T[h][c] = sum_{k<66} gTAT[k][h] * Bp[k][c]
__global__ void __launch_bounds__(256) k_i1() {
    __shared__ float Bp[66 * 36];
    int tid = threadIdx.x;
    int bi = blockIdx.x;        // 512
    int img = bi >> 1, ch = bi & 1;
    for (int i = tid; i < 264; i += 256) {
        int t = i >> 3, q = i & 7;
        float4 fp = make_float4(0, 0, 0, 0), fm = make_float4(0, 0, 0, 0);
        if (t <= 31) fp = *(const float4*)&gF[((size_t)img * 64 + t) * 64 + ch * 32 + q * 4];
        if (t >= 1)  fm = *(const float4*)&gF[((size_t)img * 64 + (64 - t)) * 64 + ch * 32 + q * 4];
        float4 P = make_float4(fp.x + fm.x, fp.y + fm.y, fp.z + fm.z, fp.w + fm.w);
        float4 d = make_float4(fp.x - fm.x, fp.y - fm.y, fp.z - fm.z, fp.w - fm.w);
        *(float4*)&Bp[(2 * t) * 36 + q * 4]     = P;
        *(float4*)&Bp[(2 * t + 1) * 36 + q * 4] = make_float4(-d.y, d.x, -d.w, d.z);
    }
    __syncthreads();
    int ty = tid >> 2, tx = tid & 3;
    ull acc[4][4] = {};
    #pragma unroll 2
    for (int k = 0; k < 66; k++) {
        float4 a = *(const float4*)&gTAT[k * 256 + ty * 4];
        const ulonglong2* bw = (const ulonglong2*)&Bp[k * 36 + tx * 8];
        ulonglong2 B0 = bw[0], B1 = bw[1];
        ull b[4] = {B0.x, B0.y, B1.x, B1.y};
        ull p0 = pk(a.x), p1 = pk(a.y), p2 = pk(a.z), p3 = pk(a.w);
        #pragma unroll
        for (int j = 0; j < 4; j++) {
            fma2(acc[0][j], p0, b[j]); fma2(acc[1][j], p1, b[j]);
            fma2(acc[2][j], p2, b[j]); fma2(acc[3][j], p3, b[j]);
        }
    }
    #pragma unroll
    for (int i = 0; i < 4; i++) {
        float* o = &gT[((size_t)img * 256 + ty * 4 + i) * 64 + ch * 32 + tx * 8];
        float2 v0 = uf(acc[i][0]), v1 = uf(acc[i][1]);
        float2 v2 = uf(acc[i][2]), v3 = uf(acc[i][3]);
        *(float4*)o       = make_float4(v0.x, v0.y, v1.x, v1.y);
        *(float4*)(o + 4) = make_float4(v2.x, v2.y, v3.x, v3.y);
    }
}

// I2: block = 64 rows, all 256 w. Coalesced staging + XOR-swizzled transpose.
__global__ void __launch_bounds__(256) k_i2(float* __restrict__ out) {
    __shared__ float Tt[64 * 64];   // [k][row ^ 2*(k>>2)]
    __shared__ float Wb[64 * 128];  // [k][w]
    int tid = threadIdx.x;
    size_t r0 = (size_t)blockIdx.x * 64;   // 1024 blocks
    for (int i = tid; i < 2048; i += 256)
        ((float4*)Wb)[i] = ((const float4*)gWB2)[i];
    {
        int q = tid & 15, srow = tid >> 4;
        #pragma unroll
        for (int it = 0; it < 4; it++) {
            int row = it * 16 + srow;
            float4 v = *(const float4*)&gT[(r0 + row) * 64 + q * 4];
            int pc = row ^ (2 * q);
            Tt[(q * 4 + 0) * 64 + pc] = v.x;
            Tt[(q * 4 + 1) * 64 + pc] = v.y;
            Tt[(q * 4 + 2) * 64 + pc] = v.z;
            Tt[(q * 4 + 3) * 64 + pc] = v.w;
        }
    }
    __syncthreads();
    int ty = tid >> 3, tx = tid & 7;
    ull accA[2][8] = {}, accB[2][8] = {};
    #pragma unroll 2
    for (int k = 0; k < 32; k++) {
        float2 a = *(const float2*)&Tt[k * 64 + ((ty * 2) ^ (2 * (k >> 2)))];
        ull p0 = pk(a.x), p1 = pk(a.y);
        #pragma unroll
        for (int g = 0; g < 4; g++) {
            ulonglong2 B = *(const ulonglong2*)&Wb[k * 128 + g * 32 + tx * 4];
            fma2(accA[0][2 * g], p0, B.x); fma2(accA[0][2 * g + 1], p0, B.y);
            fma2(accA[1][2 * g], p1, B.x); fma2(accA[1][2 * g + 1], p1, B.y);
        }
    }
    #pragma unroll 2
    for (int k = 32; k < 64; k++) {
        float2 a = *(const float2*)&Tt[k * 64 + ((ty * 2) ^ (2 * (k >> 2)))];
        ull p0 = pk(a.x), p1 = pk(a.y);
        #pragma unroll
        for (int g = 0; g < 4; g++) {
            ulonglong2 B = *(const ulonglong2*)&Wb[k * 128 + g * 32 + tx * 4];
            fma2(accB[0][2 * g], p0, B.x); fma2(accB[0][2 * g + 1], p0, B.y);
            fma2(accB[1][2 * g], p1, B.x); fma2(accB[1][2 * g + 1], p1, B.y);
        }
    }
    #pragma unroll
    for (int i = 0; i < 2; i++) {
        float* o = out + (r0 + ty * 2 + i) * 256;
        #pragma unroll
        for (int g = 0; g < 4; g++) {
            float2 a0 = uf(accA[i][2 * g]), a1 = uf(accA[i][2 * g + 1]);
            float2 b0 = uf(accB[i][2 * g]), b1 = uf(accB[i][2 * g + 1]);
            int w = g * 32 + tx * 4;
            *(float4*)&o[w]       = make_float4(a0.x + b0.x, a0.y + b0.y, a1.x + b1.x, a1.y + b1.y);
            *(float4*)&o[w + 128] = make_float4(a0.x - b0.x, a0.y - b0.y, a1.x - b1.x, a1.y - b1.y);
        }
    }
}

extern "C" void kernel_launch(void* const* d_in, const int* in_sizes, int n_in,
                              void* d_out, int out_size) {
    const float* x    = (const float*)d_in[0];
    const float* kern = (const float*)d_in[1];
    const float* r    = (const float*)d_in[2];
    float* out = (float*)d_out;

    k_tables<<<69, 256>>>();
    k_f1<<<1024, 128>>>(x);
    k_f2<<<512, 288>>>();
    k_mix<<<512, 128>>>(kern, r);
    k_i1<<<512, 256>>>();
    k_i2<<<1024, 256>>>(out);
}

// round 14
// speedup vs baseline: 1.0822x; 1.0822x over previous
#include <cuda_runtime.h>
#include <math.h>

typedef unsigned long long ull;
#define IMG 256

__device__ float gZ [IMG*256*64];
__device__ float gY [IMG*64*64];
__device__ float gF [IMG*64*64];
__device__ float gT [IMG*256*64];
__device__ float gW1[128*64];
__device__ float gTb[256*68];
__device__ float gTAT[66*256];
__device__ float gWB2[64*128];

__device__ __forceinline__ ull pk(float x) {
    ull r; unsigned xi = __float_as_uint(x);
    asm("mov.b64 %0, {%1, %1};" : "=l"(r) : "r"(xi));
    return r;
}
__device__ __forceinline__ void fma2(ull& d, ull a, ull b) {
    asm("fma.rn.f32x2 %0, %1, %2, %0;" : "+l"(d) : "l"(a), "l"(b));
}
__device__ __forceinline__ float2 uf(ull v) {
    float2 f; asm("mov.b64 {%0, %1}, %2;" : "=f"(f.x), "=f"(f.y) : "l"(v));
    return f;
}
__device__ __forceinline__ int k2map(int p) { return (p < 16) ? 2 * p : 2 * (p - 16) + 1; }

__global__ void k_tables() {
    int idx = blockIdx.x * 256 + threadIdx.x;  // 69*256
    const float W0 = 6.2831853071795864769f / 256.0f;
    if (idx < 8192) {           // gW1 [w<128][c p-order]
        int w = idx >> 6, c = idx & 63;
        int k2 = k2map(c >> 1);
        float s, cc; sincosf(((k2 * w) & 255) * W0, &s, &cc);
        gW1[idx] = (c & 1) ? -s : cc;
    }
    if (idx < 256 * 68) {       // gTb [h][2t+s], t<=32
        int h = idx / 68, tr = idx % 68;
        int t = tr >> 1; float v = 0.f;
        if (t <= 32) { float s, cc; sincosf(((t * h) & 255) * W0, &s, &cc); v = (tr & 1) ? s : cc; }
        gTb[idx] = v;
    }
    if (idx < 66 * 256) {       // gTAT [k<66][h] /16
        int k = idx >> 8, h = idx & 255;
        int t = k >> 1;
        float s, cc; sincosf(((t * h) & 255) * W0, &s, &cc);
        gTAT[idx] = ((k & 1) ? s : cc) * 0.0625f;
    }
    if (idx < 8192) {           // gWB2 [kk p-order][w<128]
        int kk = idx >> 7, w = idx & 127;
        int k2 = k2map(kk >> 1);
        float s, cc; sincosf(((k2 * w) & 255) * W0, &s, &cc);
        float v;
        if ((kk & 1) == 0) v = ((k2 == 0) ? 1.0f : 2.0f) * 0.0625f * cc;
        else               v = (k2 == 0) ? 0.0f : -0.125f * s;
        gWB2[idx] = v;
    }
}

// F1: 128 rows x 64 cols per block (512 blocks, 256 threads). R12-best config.
__global__ void __launch_bounds__(256) k_f1(const float* __restrict__ x) {
    __shared__ __align__(16) float Ut[16 * 128];  // [k][row^swz]
    __shared__ __align__(16) float Vt[16 * 128];
    __shared__ __align__(16) float Ws[128 * 64];  // [w][c]
    int tid = threadIdx.x;
    size_t r0 = (size_t)blockIdx.x * 128;
    for (int i = tid; i < 2048; i += 256)
        ((float4*)Ws)[i] = ((const float4*)gW1)[i];
    int ty = tid >> 3, tx = tid & 7;      // compute roles
    int q = tid & 3, srow = tid >> 2;     // staging roles
    int pr0 = srow ^ (q << 3), pr1 = (srow + 64) ^ (q << 3), kb = q * 4;
    float4 pa0, pb0, pa1, pb1;            // prefetch registers
    {
        const float* xp0 = x + (r0 + srow) * 256 + q * 4;
        const float* xp1 = x + (r0 + srow + 64) * 256 + q * 4;
        pa0 = *(const float4*)xp0; pb0 = *(const float4*)(xp0 + 128);
        pa1 = *(const float4*)xp1; pb1 = *(const float4*)(xp1 + 128);
    }
    ull acc[4][4] = {};
    for (int kt = 0; kt < 8; kt++) {
        __syncthreads();   // prev compute done reading smem (and Ws ready on kt=0)
        Ut[(kb + 0) * 128 + pr0] = pa0.x + pb0.x; Vt[(kb + 0) * 128 + pr0] = pa0.x - pb0.x;
        Ut[(kb + 1) * 128 + pr0] = pa0.y + pb0.y; Vt[(kb + 1) * 128 + pr0] = pa0.y - pb0.y;
        Ut[(kb + 2) * 128 + pr0] = pa0.z + pb0.z; Vt[(kb + 2) * 128 + pr0] = pa0.z - pb0.z;
        Ut[(kb + 3) * 128 + pr0] = pa0.w + pb0.w; Vt[(kb + 3) * 128 + pr0] = pa0.w - pb0.w;
        Ut[(kb + 0) * 128 + pr1] = pa1.x + pb1.x; Vt[(kb + 0) * 128 + pr1] = pa1.x - pb1.x;
        Ut[(kb + 1) * 128 + pr1] = pa1.y + pb1.y; Vt[(kb + 1) * 128 + pr1] = pa1.y - pb1.y;
        Ut[(kb + 2) * 128 + pr1] = pa1.z + pb1.z; Vt[(kb + 2) * 128 + pr1] = pa1.z - pb1.z;
        Ut[(kb + 3) * 128 + pr1] = pa1.w + pb1.w; Vt[(kb + 3) * 128 + pr1] = pa1.w - pb1.w;
        __syncthreads();
        if (kt < 7) {      // prefetch next chunk; latency hidden by compute below
            const float* xp0 = x + (r0 + srow) * 256 + (kt + 1) * 16 + q * 4;
            const float* xp1 = x + (r0 + srow + 64) * 256 + (kt + 1) * 16 + q * 4;
            pa0 = *(const float4*)xp0; pb0 = *(const float4*)(xp0 + 128);
            pa1 = *(const float4*)xp1; pb1 = *(const float4*)(xp1 + 128);
        }
        #pragma unroll 4
        for (int k = 0; k < 16; k++) {
            int sw = ((k >> 2) & 3) << 3;
            int ar_ = (ty * 4) ^ sw;
            float4 au = *(const float4*)&Ut[k * 128 + ar_];
            float4 av = *(const float4*)&Vt[k * 128 + ar_];
            const float* Wk = Ws + (kt * 16 + k) * 64;
            ulonglong2 BU = *(const ulonglong2*)&Wk[tx * 4];
            ulonglong2 BV = *(const ulonglong2*)&Wk[32 + tx * 4];
            ull pu0 = pk(au.x), pu1 = pk(au.y), pu2 = pk(au.z), pu3 = pk(au.w);
            ull pv0 = pk(av.x), pv1 = pk(av.y), pv2 = pk(av.z), pv3 = pk(av.w);
            fma2(acc[0][0], pu0, BU.x); fma2(acc[0][1], pu0, BU.y);
            fma2(acc[1][0], pu1, BU.x); fma2(acc[1][1], pu1, BU.y);
            fma2(acc[2][0], pu2, BU.x); fma2(acc[2][1], pu2, BU.y);
            fma2(acc[3][0], pu3, BU.x); fma2(acc[3][1], pu3, BU.y);
            fma2(acc[0][2], pv0, BV.x); fma2(acc[0][3], pv0, BV.y);
            fma2(acc[1][2], pv1, BV.x); fma2(acc[1][3], pv1, BV.y);
            fma2(acc[2][2], pv2, BV.x); fma2(acc[2][3], pv2, BV.y);
            fma2(acc[3][2], pv3, BV.x); fma2(acc[3][3], pv3, BV.y);
        }
    }
    #pragma unroll
    for (int i = 0; i < 4; i++) {
        float* o = &gZ[(r0 + ty * 4 + i) * 64];
        float2 u0 = uf(acc[i][0]), u1 = uf(acc[i][1]);
        float2 v0 = uf(acc[i][2]), v1 = uf(acc[i][3]);
        *(float4*)&o[tx * 4]      = make_float4(u0.x, u0.y, u1.x, u1.y);
        *(float4*)&o[32 + tx * 4] = make_float4(v0.x, v0.y, v1.x, v1.y);
    }
}

// F2: grid (img, colhalf). out rows 2t(cos)/2t+1(sin) per thread, reconstruct Y(+t)/Y(-t).
__global__ void __launch_bounds__(288) k_f2() {
    __shared__ float Tbs[64 * 68];
    __shared__ float Zs[64 * 32];
    int tid = threadIdx.x;
    int bi = blockIdx.x;             // 512
    int img = bi >> 1, ch = bi & 1;
    int ty = tid >> 3, tx = tid & 7;
    int tyc = (ty <= 32) ? ty : 32;
    ull acc[2][2] = {};
    for (int hc = 0; hc < 4; hc++) {
        __syncthreads();
        for (int i = tid; i < 512; i += 288) {
            int row = i >> 3, q = i & 7;
            *(float4*)&Zs[row * 32 + q * 4] =
                *(const float4*)&gZ[((size_t)img * 256 + hc * 64 + row) * 64 + ch * 32 + q * 4];
        }
        for (int i = tid; i < 1088; i += 288) {
            int row = i / 17, q = i % 17;
            *(float4*)&Tbs[row * 68 + q * 4] = *(const float4*)&gTb[(hc * 64 + row) * 68 + q * 4];
        }
        __syncthreads();
        #pragma unroll 4
        for (int k = 0; k < 64; k++) {
            float2 a = *(const float2*)&Tbs[k * 68 + tyc * 2];
            ulonglong2 B = *(const ulonglong2*)&Zs[k * 32 + tx * 4];
            ull pc = pk(a.x), ps = pk(a.y);
            fma2(acc[0][0], pc, B.x); fma2(acc[0][1], pc, B.y);
            fma2(acc[1][0], ps, B.x); fma2(acc[1][1], ps, B.y);
        }
    }
    if (ty <= 32) {
        int t = ty;
        float2 C0 = uf(acc[0][0]), C1 = uf(acc[0][1]);
        float2 S0 = uf(acc[1][0]), S1 = uf(acc[1][1]);
        const float n = 0.00390625f;
        float4 yp = make_float4((C0.x + S0.y) * n, (C0.y - S0.x) * n,
                                (C1.x + S1.y) * n, (C1.y - S1.x) * n);
        float4 ym = make_float4((C0.x - S0.y) * n, (C0.y + S0.x) * n,
                                (C1.x - S1.y) * n, (C1.y + S1.x) * n);
        int c = ch * 32 + tx * 4;
        if (t < 32) *(float4*)&gY[((size_t)img * 64 + t) * 64 + c] = yp;
        if (t >= 1) *(float4*)&gY[((size_t)img * 64 + (64 - t)) * 64 + c] = ym;
    }
}

// Mix (fused kernel^r + G). grid 512 = (k1i, kq-quad q4); 256 threads (b,c).
__global__ void __launch_bounds__(256) k_mix(const float* __restrict__ kern, const float* __restrict__ rp) {
    __shared__ float Ys[8][32][8];   // [b][c][2*kq], 4 kq per block
    __shared__ float KS[32][8];      // staged kern^r [j][2*kq]
    __shared__ float Gr[32][5], Gi[32][5];
    __shared__ float tw[64];
    int tid = threadIdx.x;
    int bi = blockIdx.x;             // 512
    int k1i = bi >> 3, q4 = bi & 7;
    int s_ = (k1i < 32) ? 0 : 1;
    int m1 = k1i & 31;
    int b = tid >> 5, c = tid & 31;
    if (tid < 32) {
        float s, cc; sincosf(tid * (6.2831853071795864769f / 32.0f), &s, &cc);
        tw[2 * tid] = cc; tw[2 * tid + 1] = s;
    }
    {   // stage Y
        const float4* ysrc = (const float4*)(gY + ((size_t)(b * 32 + c) * 64 + k1i) * 64 + q4 * 8);
        float4* dst = (float4*)&Ys[b][c][0];
        dst[0] = ysrc[0]; dst[1] = ysrc[1];
    }
    if (tid < 128) {   // stage kern tile with pow applied (one LDG.64 per thread)
        int j = tid >> 2, kq = tid & 3;
        int m2 = k2map(q4 * 4 + kq);
        const float* kp = kern + (((size_t)(s_ * 32 + j) * 32 + m1) * 32 + m2) * 2;
        float cr = kp[0], ci = kp[1];
        float r = *rp;
        if (r != 1.0f) {
            float mv = cr * cr + ci * ci;
            if (mv == 0.0f) { cr = 0.0f; ci = 0.0f; }
            else {
                float mag = expf(0.5f * r * logf(mv));
                float th = atan2f(ci, cr) * r;
                float sn, cs; sincosf(th, &sn, &cs);
                cr = mag * cs; ci = mag * sn;
            }
        }
        KS[j][2 * kq] = cr; KS[j][2 * kq + 1] = ci;
    }
    __syncthreads();
    if (tid < 128) {   // G[d][kq] = (1/32) sum_j tw[jd] * KS[j][kq]
        int d = tid >> 2, kq = tid & 3;
        float ar = 0.f, ai = 0.f;
        #pragma unroll 4
        for (int j = 0; j < 32; j++) {
            int a = (j * d) & 31;
            float twr = tw[2 * a], twi = tw[2 * a + 1];
            float cr = KS[j][2 * kq], ci = KS[j][2 * kq + 1];
            ar += twr * cr - twi * ci;
            ai += twr * ci + twi * cr;
        }
        Gr[d][kq] = ar * 0.03125f; Gi[d][kq] = ai * 0.03125f;
    }
    __syncthreads();
    float ar[4] = {}, ai[4] = {};
    for (int cc = 0; cc < 32; cc++) {
        int d = (c - cc) & 31;
        #pragma unroll
        for (int kq = 0; kq < 4; kq++) {
            float gr = Gr[d][kq], gim = Gi[d][kq];
            float yr = Ys[b][cc][2 * kq], yi = Ys[b][cc][2 * kq + 1];
            ar[kq] += gr * yr - gim * yi;
            ai[kq] += gr * yi + gim * yr;
        }
    }
    float* fo = gF + ((size_t)(b * 32 + c) * 64 + k1i) * 64 + q4 * 8;
    #pragma unroll
    for (int kq = 0; kq < 4; kq++) { fo[2 * kq] = ar[kq]; fo[2 * kq + 1] = ai[kq]; }
}

// I1: T[h][c] = sum_{k<66} gTAT[k][h] * Bp[k][c]
__global__ void __launch_bounds__(256) k_i1() {
    __shared__ float Bp[66 * 36];
    int tid = threadIdx.x;
    int bi = blockIdx.x;        // 512
    int img = bi >> 1, ch = bi & 1;
    for (int i = tid; i < 264; i += 256) {
        int t = i >> 3, q = i & 7;
        float4 fp = make_float4(0, 0, 0, 0), fm = make_float4(0, 0, 0, 0);
        if (t <= 31) fp = *(const float4*)&gF[((size_t)img * 64 + t) * 64 + ch * 32 + q * 4];
        if (t >= 1)  fm = *(const float4*)&gF[((size_t)img * 64 + (64 - t)) * 64 + ch * 32 + q * 4];
        float4 P = make_float4(fp.x + fm.x, fp.y + fm.y, fp.z + fm.z, fp.w + fm.w);
        float4 d = make_float4(fp.x - fm.x, fp.y - fm.y, fp.z - fm.z, fp.w - fm.w);
        *(float4*)&Bp[(2 * t) * 36 + q * 4]     = P;
        *(float4*)&Bp[(2 * t + 1) * 36 + q * 4] = make_float4(-d.y, d.x, -d.w, d.z);
    }
    __syncthreads();
    int ty = tid >> 2, tx = tid & 3;
    ull acc[4][4] = {};
    #pragma unroll 2
    for (int k = 0; k < 66; k++) {
        float4 a = *(const float4*)&gTAT[k * 256 + ty * 4];
        const ulonglong2* bw = (const ulonglong2*)&Bp[k * 36 + tx * 8];
        ulonglong2 B0 = bw[0], B1 = bw[1];
        ull b[4] = {B0.x, B0.y, B1.x, B1.y};
        ull p0 = pk(a.x), p1 = pk(a.y), p2 = pk(a.z), p3 = pk(a.w);
        #pragma unroll
        for (int j = 0; j < 4; j++) {
            fma2(acc[0][j], p0, b[j]); fma2(acc[1][j], p1, b[j]);
            fma2(acc[2][j], p2, b[j]); fma2(acc[3][j], p3, b[j]);
        }
    }
    #pragma unroll
    for (int i = 0; i < 4; i++) {
        float* o = &gT[((size_t)img * 256 + ty * 4 + i) * 64 + ch * 32 + tx * 8];
        float2 v0 = uf(acc[i][0]), v1 = uf(acc[i][1]);
        float2 v2 = uf(acc[i][2]), v3 = uf(acc[i][3]);
        *(float4*)o       = make_float4(v0.x, v0.y, v1.x, v1.y);
        *(float4*)(o + 4) = make_float4(v2.x, v2.y, v3.x, v3.y);
    }
}

// I2: block = 64 rows, all 256 w. Coalesced staging + XOR-swizzled transpose.
__global__ void __launch_bounds__(256) k_i2(float* __restrict__ out) {
    __shared__ float Tt[64 * 64];   // [k][row ^ 2*(k>>2)]
    __shared__ float Wb[64 * 128];  // [k][w]
    int tid = threadIdx.x;
    size_t r0 = (size_t)blockIdx.x * 64;   // 1024 blocks
    for (int i = tid; i < 2048; i += 256)
        ((float4*)Wb)[i] = ((const float4*)gWB2)[i];
    {
        int q = tid & 15, srow = tid >> 4;
        #pragma unroll
        for (int it = 0; it < 4; it++) {
            int row = it * 16 + srow;
            float4 v = *(const float4*)&gT[(r0 + row) * 64 + q * 4];
            int pc = row ^ (2 * q);
            Tt[(q * 4 + 0) * 64 + pc] = v.x;
            Tt[(q * 4 + 1) * 64 + pc] = v.y;
            Tt[(q * 4 + 2) * 64 + pc] = v.z;
            Tt[(q * 4 + 3) * 64 + pc] = v.w;
        }
    }
    __syncthreads();
    int ty = tid >> 3, tx = tid & 7;
    ull accA[2][8] = {}, accB[2][8] = {};
    #pragma unroll 2
    for (int k = 0; k < 32; k++) {
        float2 a = *(const float2*)&Tt[k * 64 + ((ty * 2) ^ (2 * (k >> 2)))];
        ull p0 = pk(a.x), p1 = pk(a.y);
        #pragma unroll
        for (int g = 0; g < 4; g++) {
            ulonglong2 B = *(const ulonglong2*)&Wb[k * 128 + g * 32 + tx * 4];
            fma2(accA[0][2 * g], p0, B.x); fma2(accA[0][2 * g + 1], p0, B.y);
            fma2(accA[1][2 * g], p1, B.x); fma2(accA[1][2 * g + 1], p1, B.y);
        }
    }
    #pragma unroll 2
    for (int k = 32; k < 64; k++) {
        float2 a = *(const float2*)&Tt[k * 64 + ((ty * 2) ^ (2 * (k >> 2)))];
        ull p0 = pk(a.x), p1 = pk(a.y);
        #pragma unroll
        for (int g = 0; g < 4; g++) {
            ulonglong2 B = *(const ulonglong2*)&Wb[k * 128 + g * 32 + tx * 4];
            fma2(accB[0][2 * g], p0, B.x); fma2(accB[0][2 * g + 1], p0, B.y);
            fma2(accB[1][2 * g], p1, B.x); fma2(accB[1][2 * g + 1], p1, B.y);
        }
    }
    #pragma unroll
    for (int i = 0; i < 2; i++) {
        float* o = out + (r0 + ty * 2 + i) * 256;
        #pragma unroll
        for (int g = 0; g < 4; g++) {
            float2 a0 = uf(accA[i][2 * g]), a1 = uf(accA[i][2 * g + 1]);
            float2 b0 = uf(accB[i][2 * g]), b1 = uf(accB[i][2 * g + 1]);
            int w = g * 32 + tx * 4;
            *(float4*)&o[w]       = make_float4(a0.x + b0.x, a0.y + b0.y, a1.x + b1.x, a1.y + b1.y);
            *(float4*)&o[w + 128] = make_float4(a0.x - b0.x, a0.y - b0.y, a1.x - b1.x, a1.y - b1.y);
        }
    }
}

extern "C" void kernel_launch(void* const* d_in, const int* in_sizes, int n_in,
                              void* d_out, int out_size) {
    const float* x    = (const float*)d_in[0];
    const float* kern = (const float*)d_in[1];
    const float* r    = (const float*)d_in[2];
    float* out = (float*)d_out;

    k_tables<<<69, 256>>>();
    k_f1<<<512, 256>>>(x);
    k_f2<<<512, 288>>>();
    k_mix<<<512, 256>>>(kern, r);
    k_i1<<<512, 256>>>();
    k_i2<<<1024, 256>>>(out);
}